// round 11
// baseline (speedup 1.0000x reference)
#include <cuda_runtime.h>
#include <cstdint>

// Problem constants (fixed by the reference: B=4, T=2048, S=4, D=1024)
#define BT      8192        // B*T
#define SDIM    4
#define DDIM    1024
#define DVEC    256         // D/4 float4 per row
#define SINKHORN_ITERS 20
#define EPS_SK  1e-8f

// Device-side scratch (allocation-free rule: use __device__ globals)
__device__ float d_M[16];               // M[sp*4+s] = (sp==s) + a_res*P[sp][s]
__device__ float d_g[4];                // alpha_pos * H_pos[s]
__device__ float d_biasC[SDIM * DDIM];  // bias_res + bias_pos, [s][d]

__device__ __forceinline__ float rcp_approx(float x) {
    float r;
    asm("rcp.approx.f32 %0, %1;" : "=f"(r) : "f"(x));
    return r;
}

// ---------------------------------------------------------------------------
// Prep (~1us): warp-parallel 4x4 Sinkhorn on lanes 0..15 (shfl reductions,
// rcp.approx) while the whole 256-thread block folds the 16KB bias via float4.
// ---------------------------------------------------------------------------
__global__ __launch_bounds__(256)
void prep_kernel(const float*  __restrict__ H_res,
                 const float*  __restrict__ H_pos,
                 const float*  __restrict__ alpha_res,
                 const float*  __restrict__ alpha_pos,
                 const float4* __restrict__ br,
                 const float4* __restrict__ bp)
{
    const unsigned tid = threadIdx.x;

    // Bias fold: 1024 float4, 4 per thread
    float4* biasC4 = reinterpret_cast<float4*>(d_biasC);
    #pragma unroll
    for (int i = 0; i < 4; i++) {
        unsigned j = tid + i * 256;
        float4 a = __ldg(br + j);
        float4 c = __ldg(bp + j);
        float4 b;
        b.x = a.x + c.x; b.y = a.y + c.y; b.z = a.z + c.z; b.w = a.w + c.w;
        biasC4[j] = b;
    }

    // Warp 0, lanes 0..15: Sinkhorn. lane = r*4 + c holds P[r][c].
    if (tid < 16) {
        const unsigned lane = tid;
        float h = __ldg(H_res + lane);
        float m = fmaxf(h, __shfl_xor_sync(0xffffu, h, 1));
        m = fmaxf(m, __shfl_xor_sync(0xffffu, m, 2));
        float v = __expf(h - m);
        #pragma unroll 1
        for (int it = 0; it < SINKHORN_ITERS; it++) {
            float s = v + __shfl_xor_sync(0xffffu, v, 1);   // row sum (over c)
            s += __shfl_xor_sync(0xffffu, s, 2);
            v *= rcp_approx(s + EPS_SK);
            float t = v + __shfl_xor_sync(0xffffu, v, 4);   // col sum (over r)
            t += __shfl_xor_sync(0xffffu, t, 8);
            v *= rcp_approx(t + EPS_SK);
        }
        float ar = __ldg(alpha_res);
        float diag = ((lane >> 2) == (lane & 3)) ? 1.0f : 0.0f;
        d_M[lane] = diag + ar * v;
        if (lane < 4)
            d_g[lane] = __ldg(alpha_pos) * __ldg(H_pos + lane);
    }
}

// ---------------------------------------------------------------------------
// Main kernel — R10 body (grid 8192, 5 front-batched streaming loads,
// precombined bias, .cs store hints) with the single variable under test:
// __launch_bounds__(256, 5) caps regs at 51 -> 5 CTAs = 40 warps/SM (+25%
// warp-level memory parallelism vs the 4-CTA/64-reg configuration).
//   out[bt,s,dv] = sum_sp M[sp][s]*x[bt,sp,dv] + g[s]*lo[bt,dv] + biasC[s,dv]
// ---------------------------------------------------------------------------
__global__ __launch_bounds__(256, 5)
void mhc_residual_kernel(const float4* __restrict__ x,
                         const float4* __restrict__ lo,
                         float4* __restrict__ out)
{
    __shared__ float sM[16];
    __shared__ float sg[4];
    if (threadIdx.x < 16) sM[threadIdx.x] = d_M[threadIdx.x];
    if (threadIdx.x < 4)  sg[threadIdx.x] = d_g[threadIdx.x];
    __syncthreads();

    unsigned idx = blockIdx.x * blockDim.x + threadIdx.x;  // 0 .. BT*DVEC-1
    unsigned dvec = idx & (DVEC - 1);
    unsigned bt   = idx >> 8;  // log2(DVEC) = 8

    const float4* xr = x + (size_t)bt * (SDIM * DVEC) + dvec;
    float4 x0 = __ldcs(xr + 0 * DVEC);
    float4 x1 = __ldcs(xr + 1 * DVEC);
    float4 x2 = __ldcs(xr + 2 * DVEC);
    float4 x3 = __ldcs(xr + 3 * DVEC);
    float4 l  = __ldcs(lo + (size_t)bt * DVEC + dvec);

    const float4* bC = reinterpret_cast<const float4*>(d_biasC) + dvec;
    float4* outr = out + (size_t)bt * (SDIM * DVEC) + dvec;

#pragma unroll
    for (int s = 0; s < 4; s++) {
        float m0 = sM[0 * 4 + s];
        float m1 = sM[1 * 4 + s];
        float m2 = sM[2 * 4 + s];
        float m3 = sM[3 * 4 + s];
        float g  = sg[s];
        float4 b = __ldg(bC + s * DVEC);
        float4 o;
        o.x = fmaf(m0, x0.x, fmaf(m1, x1.x, fmaf(m2, x2.x, fmaf(m3, x3.x, fmaf(g, l.x, b.x)))));
        o.y = fmaf(m0, x0.y, fmaf(m1, x1.y, fmaf(m2, x2.y, fmaf(m3, x3.y, fmaf(g, l.y, b.y)))));
        o.z = fmaf(m0, x0.z, fmaf(m1, x1.z, fmaf(m2, x2.z, fmaf(m3, x3.z, fmaf(g, l.z, b.z)))));
        o.w = fmaf(m0, x0.w, fmaf(m1, x1.w, fmaf(m2, x2.w, fmaf(m3, x3.w, fmaf(g, l.w, b.w)))));
        __stcs(outr + s * DVEC, o);
    }
}

// ---------------------------------------------------------------------------
// Launch. Inputs per metadata order:
//   0: x (B,T,S,D) f32   1: layer_output (B,T,D) f32   2: H_res (S,S) f32
//   3: H_pos (S,1) f32   4: alpha_res f32 scalar        5: alpha_pos f32 scalar
//   6: bias_res (S,D)    7: bias_pos (S,D)
// ---------------------------------------------------------------------------
extern "C" void kernel_launch(void* const* d_in, const int* in_sizes, int n_in,
                              void* d_out, int out_size)
{
    const float* x         = (const float*)d_in[0];
    const float* lo        = (const float*)d_in[1];
    const float* H_res     = (const float*)d_in[2];
    const float* H_pos     = (const float*)d_in[3];
    const float* alpha_res = (const float*)d_in[4];
    const float* alpha_pos = (const float*)d_in[5];
    const float* bias_res  = (const float*)d_in[6];
    const float* bias_pos  = (const float*)d_in[7];
    float* out             = (float*)d_out;

    prep_kernel<<<1, 256>>>(H_res, H_pos, alpha_res, alpha_pos,
                            (const float4*)bias_res, (const float4*)bias_pos);

    const unsigned total = BT * DVEC;          // 2,097,152 threads
    const unsigned threads = 256;
    mhc_residual_kernel<<<total / threads, threads>>>(
        (const float4*)x, (const float4*)lo, (float4*)out);
}

// round 12
// speedup vs baseline: 1.0036x; 1.0036x over previous
#include <cuda_runtime.h>
#include <cstdint>

// Problem constants (fixed by the reference: B=4, T=2048, S=4, D=1024)
#define BT      8192        // B*T
#define SDIM    4
#define DDIM    1024
#define DVEC    256         // D/4 float4 per row
#define SINKHORN_ITERS 20
#define EPS_SK  1e-8f

// Device-side scratch (allocation-free rule: use __device__ globals)
__device__ float d_M[16];               // M[sp*4+s] = (sp==s) + a_res*P[sp][s]
__device__ float d_g[4];                // alpha_pos * H_pos[s]
__device__ float d_biasC[SDIM * DDIM];  // bias_res + bias_pos, [s][d]

__device__ __forceinline__ float rcp_approx(float x) {
    float r;
    asm("rcp.approx.f32 %0, %1;" : "=f"(r) : "f"(x));
    return r;
}

// ---------------------------------------------------------------------------
// Prep (~1us): warp-parallel 4x4 Sinkhorn on lanes 0..15 (shfl reductions,
// rcp.approx) while the whole 256-thread block folds the 16KB bias via float4.
// ---------------------------------------------------------------------------
__global__ __launch_bounds__(256)
void prep_kernel(const float*  __restrict__ H_res,
                 const float*  __restrict__ H_pos,
                 const float*  __restrict__ alpha_res,
                 const float*  __restrict__ alpha_pos,
                 const float4* __restrict__ br,
                 const float4* __restrict__ bp)
{
    const unsigned tid = threadIdx.x;

    // Bias fold: 1024 float4, 4 per thread
    float4* biasC4 = reinterpret_cast<float4*>(d_biasC);
    #pragma unroll
    for (int i = 0; i < 4; i++) {
        unsigned j = tid + i * 256;
        float4 a = __ldg(br + j);
        float4 c = __ldg(bp + j);
        float4 b;
        b.x = a.x + c.x; b.y = a.y + c.y; b.z = a.z + c.z; b.w = a.w + c.w;
        biasC4[j] = b;
    }

    // Warp 0, lanes 0..15: Sinkhorn. lane = r*4 + c holds P[r][c].
    if (tid < 16) {
        const unsigned lane = tid;
        float h = __ldg(H_res + lane);
        float m = fmaxf(h, __shfl_xor_sync(0xffffu, h, 1));
        m = fmaxf(m, __shfl_xor_sync(0xffffu, m, 2));
        float v = __expf(h - m);
        #pragma unroll 1
        for (int it = 0; it < SINKHORN_ITERS; it++) {
            float s = v + __shfl_xor_sync(0xffffu, v, 1);   // row sum (over c)
            s += __shfl_xor_sync(0xffffu, s, 2);
            v *= rcp_approx(s + EPS_SK);
            float t = v + __shfl_xor_sync(0xffffu, v, 4);   // col sum (over r)
            t += __shfl_xor_sync(0xffffu, t, 8);
            v *= rcp_approx(t + EPS_SK);
        }
        float ar = __ldg(alpha_res);
        float diag = ((lane >> 2) == (lane & 3)) ? 1.0f : 0.0f;
        d_M[lane] = diag + ar * v;
        if (lane < 4)
            d_g[lane] = __ldg(alpha_pos) * __ldg(H_pos + lane);
    }
}

// ---------------------------------------------------------------------------
// Main kernel — the measured optimum (R10): grid 8192 (one block per bt
// tile), 5 front-batched streaming loads (__ldcs), precombined bias via
// __ldg (L1/L2-resident), streaming stores (__stcs), 64 regs / 4 CTAs/SM
// (RF exactly full, zero spills). Register sweep on both sides confirmed
// this as the sweet spot (48r:46.2us, 64r:41.0us, 66r:44.1us, 80r:45.0us).
//   out[bt,s,dv] = sum_sp M[sp][s]*x[bt,sp,dv] + g[s]*lo[bt,dv] + biasC[s,dv]
// ---------------------------------------------------------------------------
__global__ __launch_bounds__(256, 4)
void mhc_residual_kernel(const float4* __restrict__ x,
                         const float4* __restrict__ lo,
                         float4* __restrict__ out)
{
    __shared__ float sM[16];
    __shared__ float sg[4];
    if (threadIdx.x < 16) sM[threadIdx.x] = d_M[threadIdx.x];
    if (threadIdx.x < 4)  sg[threadIdx.x] = d_g[threadIdx.x];
    __syncthreads();

    unsigned idx = blockIdx.x * blockDim.x + threadIdx.x;  // 0 .. BT*DVEC-1
    unsigned dvec = idx & (DVEC - 1);
    unsigned bt   = idx >> 8;  // log2(DVEC) = 8

    const float4* xr = x + (size_t)bt * (SDIM * DVEC) + dvec;
    float4 x0 = __ldcs(xr + 0 * DVEC);
    float4 x1 = __ldcs(xr + 1 * DVEC);
    float4 x2 = __ldcs(xr + 2 * DVEC);
    float4 x3 = __ldcs(xr + 3 * DVEC);
    float4 l  = __ldcs(lo + (size_t)bt * DVEC + dvec);

    const float4* bC = reinterpret_cast<const float4*>(d_biasC) + dvec;
    float4* outr = out + (size_t)bt * (SDIM * DVEC) + dvec;

#pragma unroll
    for (int s = 0; s < 4; s++) {
        float m0 = sM[0 * 4 + s];
        float m1 = sM[1 * 4 + s];
        float m2 = sM[2 * 4 + s];
        float m3 = sM[3 * 4 + s];
        float g  = sg[s];
        float4 b = __ldg(bC + s * DVEC);
        float4 o;
        o.x = fmaf(m0, x0.x, fmaf(m1, x1.x, fmaf(m2, x2.x, fmaf(m3, x3.x, fmaf(g, l.x, b.x)))));
        o.y = fmaf(m0, x0.y, fmaf(m1, x1.y, fmaf(m2, x2.y, fmaf(m3, x3.y, fmaf(g, l.y, b.y)))));
        o.z = fmaf(m0, x0.z, fmaf(m1, x1.z, fmaf(m2, x2.z, fmaf(m3, x3.z, fmaf(g, l.z, b.z)))));
        o.w = fmaf(m0, x0.w, fmaf(m1, x1.w, fmaf(m2, x2.w, fmaf(m3, x3.w, fmaf(g, l.w, b.w)))));
        __stcs(outr + s * DVEC, o);
    }
}

// ---------------------------------------------------------------------------
// Launch. Inputs per metadata order:
//   0: x (B,T,S,D) f32   1: layer_output (B,T,D) f32   2: H_res (S,S) f32
//   3: H_pos (S,1) f32   4: alpha_res f32 scalar        5: alpha_pos f32 scalar
//   6: bias_res (S,D)    7: bias_pos (S,D)
// ---------------------------------------------------------------------------
extern "C" void kernel_launch(void* const* d_in, const int* in_sizes, int n_in,
                              void* d_out, int out_size)
{
    const float* x         = (const float*)d_in[0];
    const float* lo        = (const float*)d_in[1];
    const float* H_res     = (const float*)d_in[2];
    const float* H_pos     = (const float*)d_in[3];
    const float* alpha_res = (const float*)d_in[4];
    const float* alpha_pos = (const float*)d_in[5];
    const float* bias_res  = (const float*)d_in[6];
    const float* bias_pos  = (const float*)d_in[7];
    float* out             = (float*)d_out;

    prep_kernel<<<1, 256>>>(H_res, H_pos, alpha_res, alpha_pos,
                            (const float4*)bias_res, (const float4*)bias_pos);

    const unsigned total = BT * DVEC;          // 2,097,152 threads
    const unsigned threads = 256;
    mhc_residual_kernel<<<total / threads, threads>>>(
        (const float4*)x, (const float4*)lo, (float4*)out);
}

// round 13
// speedup vs baseline: 1.0054x; 1.0018x over previous
#include <cuda_runtime.h>
#include <cstdint>

// Problem constants (fixed by the reference: B=4, T=2048, S=4, D=1024)
#define BT      8192        // B*T
#define SDIM    4
#define DDIM    1024
#define DVEC    256         // D/4 float4 per row
#define SINKHORN_ITERS 20
#define EPS_SK  1e-8f

// Device-side scratch (allocation-free rule: use __device__ globals)
__device__ float4 d_Mt4[4];             // column s of M: {M[0][s],M[1][s],M[2][s],M[3][s]}
__device__ float4 d_g4;                 // {g0,g1,g2,g3} = alpha_pos * H_pos
__device__ float  d_biasC[SDIM * DDIM]; // bias_res + bias_pos, [s][d]

__device__ __forceinline__ float rcp_approx(float x) {
    float r;
    asm("rcp.approx.f32 %0, %1;" : "=f"(r) : "f"(x));
    return r;
}

// ---------------------------------------------------------------------------
// Prep (~1us): warp-parallel 4x4 Sinkhorn on lanes 0..15 (shfl reductions,
// rcp.approx) while the whole 256-thread block folds the 16KB bias via float4.
// Emits M TRANSPOSED as 4 float4 columns so the main kernel can fetch each
// output-stream's coefficients with a single broadcast LDG.128.
// ---------------------------------------------------------------------------
__global__ __launch_bounds__(256)
void prep_kernel(const float*  __restrict__ H_res,
                 const float*  __restrict__ H_pos,
                 const float*  __restrict__ alpha_res,
                 const float*  __restrict__ alpha_pos,
                 const float4* __restrict__ br,
                 const float4* __restrict__ bp)
{
    const unsigned tid = threadIdx.x;

    // Bias fold: 1024 float4, 4 per thread
    float4* biasC4 = reinterpret_cast<float4*>(d_biasC);
    #pragma unroll
    for (int i = 0; i < 4; i++) {
        unsigned j = tid + i * 256;
        float4 a = __ldg(br + j);
        float4 c = __ldg(bp + j);
        float4 b;
        b.x = a.x + c.x; b.y = a.y + c.y; b.z = a.z + c.z; b.w = a.w + c.w;
        biasC4[j] = b;
    }

    // Warp 0, lanes 0..15: Sinkhorn. lane = r*4 + c holds P[r][c].
    if (tid < 16) {
        const unsigned lane = tid;
        float h = __ldg(H_res + lane);
        float m = fmaxf(h, __shfl_xor_sync(0xffffu, h, 1));
        m = fmaxf(m, __shfl_xor_sync(0xffffu, m, 2));
        float v = __expf(h - m);
        #pragma unroll 1
        for (int it = 0; it < SINKHORN_ITERS; it++) {
            float s = v + __shfl_xor_sync(0xffffu, v, 1);   // row sum (over c)
            s += __shfl_xor_sync(0xffffu, s, 2);
            v *= rcp_approx(s + EPS_SK);
            float t = v + __shfl_xor_sync(0xffffu, v, 4);   // col sum (over r)
            t += __shfl_xor_sync(0xffffu, t, 8);
            v *= rcp_approx(t + EPS_SK);
        }
        float ar = __ldg(alpha_res);
        float diag = ((lane >> 2) == (lane & 3)) ? 1.0f : 0.0f;
        float mval = diag + ar * v;                 // M[r][c], lane = r*4 + c

        // Transpose via shfl: lane L gathers M[L%4 row-elements] of column L/4.
        // Column s needs M[0][s],M[1][s],M[2][s],M[3][s] = lanes s, 4+s, 8+s, 12+s.
        // Let lanes 0..3 each assemble one column scalar-by-scalar:
        float c0 = __shfl_sync(0xffffu, mval, (lane & 3) + 0);
        float c1 = __shfl_sync(0xffffu, mval, (lane & 3) + 4);
        float c2 = __shfl_sync(0xffffu, mval, (lane & 3) + 8);
        float c3 = __shfl_sync(0xffffu, mval, (lane & 3) + 12);
        if (lane < 4) {
            d_Mt4[lane] = make_float4(c0, c1, c2, c3);
        }
        if (lane == 0) {
            float ap = __ldg(alpha_pos);
            d_g4 = make_float4(ap * __ldg(H_pos + 0), ap * __ldg(H_pos + 1),
                               ap * __ldg(H_pos + 2), ap * __ldg(H_pos + 3));
        }
    }
}

// ---------------------------------------------------------------------------
// Main kernel — R10/R12 body (grid 8192, 5 front-batched streaming loads,
// precombined bias, .cs hints, 64-reg / 4-CTA envelope) with the startup
// barrier REMOVED: no shared memory, no __syncthreads. The 5 DRAM loads
// issue as the block's first instructions; M columns + g arrive as warp-
// uniform broadcast LDG.128s (L1-hit after the first warp), so fresh CTAs
// start filling the DRAM queue ~700 cycles earlier at every block switch.
//   out[bt,s,dv] = sum_sp M[sp][s]*x[bt,sp,dv] + g[s]*lo[bt,dv] + biasC[s,dv]
// ---------------------------------------------------------------------------
__global__ __launch_bounds__(256, 4)
void mhc_residual_kernel(const float4* __restrict__ x,
                         const float4* __restrict__ lo,
                         float4* __restrict__ out)
{
    unsigned idx = blockIdx.x * blockDim.x + threadIdx.x;  // 0 .. BT*DVEC-1
    unsigned dvec = idx & (DVEC - 1);
    unsigned bt   = idx >> 8;  // log2(DVEC) = 8

    // DRAM-bound loads issue FIRST — nothing ahead of them.
    const float4* xr = x + (size_t)bt * (SDIM * DVEC) + dvec;
    float4 x0 = __ldcs(xr + 0 * DVEC);
    float4 x1 = __ldcs(xr + 1 * DVEC);
    float4 x2 = __ldcs(xr + 2 * DVEC);
    float4 x3 = __ldcs(xr + 3 * DVEC);
    float4 l  = __ldcs(lo + (size_t)bt * DVEC + dvec);

    // Warp-uniform broadcast loads (L1-resident): g and the 4 M columns.
    float4 gv = __ldg(&d_g4);

    const float4* bC = reinterpret_cast<const float4*>(d_biasC) + dvec;
    float4* outr = out + (size_t)bt * (SDIM * DVEC) + dvec;

#pragma unroll
    for (int s = 0; s < 4; s++) {
        float4 mc = __ldg(&d_Mt4[s]);      // {M[0][s],M[1][s],M[2][s],M[3][s]}
        float g = (s == 0) ? gv.x : (s == 1) ? gv.y : (s == 2) ? gv.z : gv.w;
        float4 b = __ldg(bC + s * DVEC);
        float4 o;
        o.x = fmaf(mc.x, x0.x, fmaf(mc.y, x1.x, fmaf(mc.z, x2.x, fmaf(mc.w, x3.x, fmaf(g, l.x, b.x)))));
        o.y = fmaf(mc.x, x0.y, fmaf(mc.y, x1.y, fmaf(mc.z, x2.y, fmaf(mc.w, x3.y, fmaf(g, l.y, b.y)))));
        o.z = fmaf(mc.x, x0.z, fmaf(mc.y, x1.z, fmaf(mc.z, x2.z, fmaf(mc.w, x3.z, fmaf(g, l.z, b.z)))));
        o.w = fmaf(mc.x, x0.w, fmaf(mc.y, x1.w, fmaf(mc.z, x2.w, fmaf(mc.w, x3.w, fmaf(g, l.w, b.w)))));
        __stcs(outr + s * DVEC, o);
    }
}

// ---------------------------------------------------------------------------
// Launch. Inputs per metadata order:
//   0: x (B,T,S,D) f32   1: layer_output (B,T,D) f32   2: H_res (S,S) f32
//   3: H_pos (S,1) f32   4: alpha_res f32 scalar        5: alpha_pos f32 scalar
//   6: bias_res (S,D)    7: bias_pos (S,D)
// ---------------------------------------------------------------------------
extern "C" void kernel_launch(void* const* d_in, const int* in_sizes, int n_in,
                              void* d_out, int out_size)
{
    const float* x         = (const float*)d_in[0];
    const float* lo        = (const float*)d_in[1];
    const float* H_res     = (const float*)d_in[2];
    const float* H_pos     = (const float*)d_in[3];
    const float* alpha_res = (const float*)d_in[4];
    const float* alpha_pos = (const float*)d_in[5];
    const float* bias_res  = (const float*)d_in[6];
    const float* bias_pos  = (const float*)d_in[7];
    float* out             = (float*)d_out;

    prep_kernel<<<1, 256>>>(H_res, H_pos, alpha_res, alpha_pos,
                            (const float4*)bias_res, (const float4*)bias_pos);

    const unsigned total = BT * DVEC;          // 2,097,152 threads
    const unsigned threads = 256;
    mhc_residual_kernel<<<total / threads, threads>>>(
        (const float4*)x, (const float4*)lo, (float4*)out);
}

// round 14
// speedup vs baseline: 1.0097x; 1.0042x over previous
#include <cuda_runtime.h>
#include <cstdint>

// Problem constants (fixed by the reference: B=4, T=2048, S=4, D=1024)
#define BT      8192        // B*T
#define SDIM    4
#define DDIM    1024
#define DVEC    256         // D/4 float4 per row
#define SINKHORN_ITERS 20
#define EPS_SK  1e-8f

// Device-side scratch (allocation-free rule: use __device__ globals)
__device__ float4 d_Mt4[4];             // column s of M: {M[0][s],M[1][s],M[2][s],M[3][s]}
__device__ float4 d_g4;                 // {g0,g1,g2,g3} = alpha_pos * H_pos
__device__ float  d_biasC[SDIM * DDIM]; // bias_res + bias_pos, [s][d]

__device__ __forceinline__ float rcp_approx(float x) {
    float r;
    asm("rcp.approx.f32 %0, %1;" : "=f"(r) : "f"(x));
    return r;
}

// ---------------------------------------------------------------------------
// Prep (~1us): warp-parallel 4x4 Sinkhorn on lanes 0..15 (shfl reductions,
// rcp.approx) while the whole 256-thread block folds the 16KB bias via float4.
// Emits M TRANSPOSED as 4 float4 columns (single broadcast LDG.128 per
// output stream in the main kernel).
// ---------------------------------------------------------------------------
__global__ __launch_bounds__(256)
void prep_kernel(const float*  __restrict__ H_res,
                 const float*  __restrict__ H_pos,
                 const float*  __restrict__ alpha_res,
                 const float*  __restrict__ alpha_pos,
                 const float4* __restrict__ br,
                 const float4* __restrict__ bp)
{
    const unsigned tid = threadIdx.x;

    // Bias fold: 1024 float4, 4 per thread
    float4* biasC4 = reinterpret_cast<float4*>(d_biasC);
    #pragma unroll
    for (int i = 0; i < 4; i++) {
        unsigned j = tid + i * 256;
        float4 a = __ldg(br + j);
        float4 c = __ldg(bp + j);
        float4 b;
        b.x = a.x + c.x; b.y = a.y + c.y; b.z = a.z + c.z; b.w = a.w + c.w;
        biasC4[j] = b;
    }

    // Warp 0, lanes 0..15: Sinkhorn. lane = r*4 + c holds P[r][c].
    if (tid < 16) {
        const unsigned lane = tid;
        float h = __ldg(H_res + lane);
        float m = fmaxf(h, __shfl_xor_sync(0xffffu, h, 1));
        m = fmaxf(m, __shfl_xor_sync(0xffffu, m, 2));
        float v = __expf(h - m);
        #pragma unroll 1
        for (int it = 0; it < SINKHORN_ITERS; it++) {
            float s = v + __shfl_xor_sync(0xffffu, v, 1);   // row sum (over c)
            s += __shfl_xor_sync(0xffffu, s, 2);
            v *= rcp_approx(s + EPS_SK);
            float t = v + __shfl_xor_sync(0xffffu, v, 4);   // col sum (over r)
            t += __shfl_xor_sync(0xffffu, t, 8);
            v *= rcp_approx(t + EPS_SK);
        }
        float ar = __ldg(alpha_res);
        float diag = ((lane >> 2) == (lane & 3)) ? 1.0f : 0.0f;
        float mval = diag + ar * v;                 // M[r][c], lane = r*4 + c

        // Transpose via shfl: column s = {lanes s, 4+s, 8+s, 12+s}
        float c0 = __shfl_sync(0xffffu, mval, (lane & 3) + 0);
        float c1 = __shfl_sync(0xffffu, mval, (lane & 3) + 4);
        float c2 = __shfl_sync(0xffffu, mval, (lane & 3) + 8);
        float c3 = __shfl_sync(0xffffu, mval, (lane & 3) + 12);
        if (lane < 4) {
            d_Mt4[lane] = make_float4(c0, c1, c2, c3);
        }
        if (lane == 0) {
            float ap = __ldg(alpha_pos);
            d_g4 = make_float4(ap * __ldg(H_pos + 0), ap * __ldg(H_pos + 1),
                               ap * __ldg(H_pos + 2), ap * __ldg(H_pos + 3));
        }
    }
}

// ---------------------------------------------------------------------------
// Main kernel — R13 barrier-free body, with CTA granularity halved:
// 128-thread blocks, grid 16384, __launch_bounds__(128, 8) -> 8 CTAs/SM at
// the same 64 regs (RF exactly full, same 32 warps/SM). Finer CTA retire/
// launch quanta: a straggler warp now strands at most 3 peers' RF slots
// instead of 7, tightening wave transitions across ~14 waves.
// Thread -> data mapping is IDENTICAL to the 256-thread version (flat idx).
//   out[bt,s,dv] = sum_sp M[sp][s]*x[bt,sp,dv] + g[s]*lo[bt,dv] + biasC[s,dv]
// ---------------------------------------------------------------------------
__global__ __launch_bounds__(128, 8)
void mhc_residual_kernel(const float4* __restrict__ x,
                         const float4* __restrict__ lo,
                         float4* __restrict__ out)
{
    unsigned idx = blockIdx.x * 128u + threadIdx.x;  // 0 .. BT*DVEC-1
    unsigned dvec = idx & (DVEC - 1);
    unsigned bt   = idx >> 8;  // log2(DVEC) = 8

    // DRAM-bound loads issue FIRST — nothing ahead of them.
    const float4* xr = x + (size_t)bt * (SDIM * DVEC) + dvec;
    float4 x0 = __ldcs(xr + 0 * DVEC);
    float4 x1 = __ldcs(xr + 1 * DVEC);
    float4 x2 = __ldcs(xr + 2 * DVEC);
    float4 x3 = __ldcs(xr + 3 * DVEC);
    float4 l  = __ldcs(lo + (size_t)bt * DVEC + dvec);

    // Warp-uniform broadcast loads (L1-resident): g and the 4 M columns.
    float4 gv = __ldg(&d_g4);

    const float4* bC = reinterpret_cast<const float4*>(d_biasC) + dvec;
    float4* outr = out + (size_t)bt * (SDIM * DVEC) + dvec;

#pragma unroll
    for (int s = 0; s < 4; s++) {
        float4 mc = __ldg(&d_Mt4[s]);      // {M[0][s],M[1][s],M[2][s],M[3][s]}
        float g = (s == 0) ? gv.x : (s == 1) ? gv.y : (s == 2) ? gv.z : gv.w;
        float4 b = __ldg(bC + s * DVEC);
        float4 o;
        o.x = fmaf(mc.x, x0.x, fmaf(mc.y, x1.x, fmaf(mc.z, x2.x, fmaf(mc.w, x3.x, fmaf(g, l.x, b.x)))));
        o.y = fmaf(mc.x, x0.y, fmaf(mc.y, x1.y, fmaf(mc.z, x2.y, fmaf(mc.w, x3.y, fmaf(g, l.y, b.y)))));
        o.z = fmaf(mc.x, x0.z, fmaf(mc.y, x1.z, fmaf(mc.z, x2.z, fmaf(mc.w, x3.z, fmaf(g, l.z, b.z)))));
        o.w = fmaf(mc.x, x0.w, fmaf(mc.y, x1.w, fmaf(mc.z, x2.w, fmaf(mc.w, x3.w, fmaf(g, l.w, b.w)))));
        __stcs(outr + s * DVEC, o);
    }
}

// ---------------------------------------------------------------------------
// Launch. Inputs per metadata order:
//   0: x (B,T,S,D) f32   1: layer_output (B,T,D) f32   2: H_res (S,S) f32
//   3: H_pos (S,1) f32   4: alpha_res f32 scalar        5: alpha_pos f32 scalar
//   6: bias_res (S,D)    7: bias_pos (S,D)
// ---------------------------------------------------------------------------
extern "C" void kernel_launch(void* const* d_in, const int* in_sizes, int n_in,
                              void* d_out, int out_size)
{
    const float* x         = (const float*)d_in[0];
    const float* lo        = (const float*)d_in[1];
    const float* H_res     = (const float*)d_in[2];
    const float* H_pos     = (const float*)d_in[3];
    const float* alpha_res = (const float*)d_in[4];
    const float* alpha_pos = (const float*)d_in[5];
    const float* bias_res  = (const float*)d_in[6];
    const float* bias_pos  = (const float*)d_in[7];
    float* out             = (float*)d_out;

    prep_kernel<<<1, 256>>>(H_res, H_pos, alpha_res, alpha_pos,
                            (const float4*)bias_res, (const float4*)bias_pos);

    const unsigned total = BT * DVEC;          // 2,097,152 threads
    mhc_residual_kernel<<<total / 128, 128>>>(
        (const float4*)x, (const float4*)lo, (float4*)out);
}

// round 15
// speedup vs baseline: 1.0146x; 1.0049x over previous
#include <cuda_runtime.h>
#include <cstdint>

// Problem constants (fixed by the reference: B=4, T=2048, S=4, D=1024)
#define BT      8192        // B*T
#define SDIM    4
#define DDIM    1024
#define DVEC    256         // D/4 float4 per row
#define SINKHORN_ITERS 20
#define EPS_SK  1e-8f

// Device-side scratch (allocation-free rule: use __device__ globals)
__device__ float4 d_Mt4[4];             // column s of M: {M[0][s],M[1][s],M[2][s],M[3][s]}
__device__ float4 d_g4;                 // {g0,g1,g2,g3} = alpha_pos * H_pos
__device__ float  d_biasC[SDIM * DDIM]; // bias_res + bias_pos, [s][d]

__device__ __forceinline__ float rcp_approx(float x) {
    float r;
    asm("rcp.approx.f32 %0, %1;" : "=f"(r) : "f"(x));
    return r;
}

// ---------------------------------------------------------------------------
// Prep (~1us): warp-parallel 4x4 Sinkhorn on lanes 0..15 (shfl reductions,
// rcp.approx) while the whole 256-thread block folds the 16KB bias via float4.
// Emits M TRANSPOSED as 4 float4 columns (single broadcast LDG.128 per
// output stream in the main kernel).
// ---------------------------------------------------------------------------
__global__ __launch_bounds__(256)
void prep_kernel(const float*  __restrict__ H_res,
                 const float*  __restrict__ H_pos,
                 const float*  __restrict__ alpha_res,
                 const float*  __restrict__ alpha_pos,
                 const float4* __restrict__ br,
                 const float4* __restrict__ bp)
{
    const unsigned tid = threadIdx.x;

    // Bias fold: 1024 float4, 4 per thread
    float4* biasC4 = reinterpret_cast<float4*>(d_biasC);
    #pragma unroll
    for (int i = 0; i < 4; i++) {
        unsigned j = tid + i * 256;
        float4 a = __ldg(br + j);
        float4 c = __ldg(bp + j);
        float4 b;
        b.x = a.x + c.x; b.y = a.y + c.y; b.z = a.z + c.z; b.w = a.w + c.w;
        biasC4[j] = b;
    }

    // Warp 0, lanes 0..15: Sinkhorn. lane = r*4 + c holds P[r][c].
    if (tid < 16) {
        const unsigned lane = tid;
        float h = __ldg(H_res + lane);
        float m = fmaxf(h, __shfl_xor_sync(0xffffu, h, 1));
        m = fmaxf(m, __shfl_xor_sync(0xffffu, m, 2));
        float v = __expf(h - m);
        #pragma unroll 1
        for (int it = 0; it < SINKHORN_ITERS; it++) {
            float s = v + __shfl_xor_sync(0xffffu, v, 1);   // row sum (over c)
            s += __shfl_xor_sync(0xffffu, s, 2);
            v *= rcp_approx(s + EPS_SK);
            float t = v + __shfl_xor_sync(0xffffu, v, 4);   // col sum (over r)
            t += __shfl_xor_sync(0xffffu, t, 8);
            v *= rcp_approx(t + EPS_SK);
        }
        float ar = __ldg(alpha_res);
        float diag = ((lane >> 2) == (lane & 3)) ? 1.0f : 0.0f;
        float mval = diag + ar * v;                 // M[r][c], lane = r*4 + c

        // Transpose via shfl: column s = {lanes s, 4+s, 8+s, 12+s}
        float c0 = __shfl_sync(0xffffu, mval, (lane & 3) + 0);
        float c1 = __shfl_sync(0xffffu, mval, (lane & 3) + 4);
        float c2 = __shfl_sync(0xffffu, mval, (lane & 3) + 8);
        float c3 = __shfl_sync(0xffffu, mval, (lane & 3) + 12);
        if (lane < 4) {
            d_Mt4[lane] = make_float4(c0, c1, c2, c3);
        }
        if (lane == 0) {
            float ap = __ldg(alpha_pos);
            d_g4 = make_float4(ap * __ldg(H_pos + 0), ap * __ldg(H_pos + 1),
                               ap * __ldg(H_pos + 2), ap * __ldg(H_pos + 3));
        }
    }
}

// ---------------------------------------------------------------------------
// Main kernel — R14 barrier-free body with CTA granularity halved AGAIN:
// 64-thread blocks, grid 32768, __launch_bounds__(64, 16) -> 16 CTAs/SM at
// the same 64 regs (RF exactly full, same 32 warps/SM). The CTA-granularity
// axis is the one knob that measurably improved the kernel (256thr: 41.2us,
// 128thr: 40.2us); this tests whether the trend continues at 64.
// Thread -> data mapping is IDENTICAL (flat idx decomposition).
//   out[bt,s,dv] = sum_sp M[sp][s]*x[bt,sp,dv] + g[s]*lo[bt,dv] + biasC[s,dv]
// ---------------------------------------------------------------------------
__global__ __launch_bounds__(64, 16)
void mhc_residual_kernel(const float4* __restrict__ x,
                         const float4* __restrict__ lo,
                         float4* __restrict__ out)
{
    unsigned idx = blockIdx.x * 64u + threadIdx.x;  // 0 .. BT*DVEC-1
    unsigned dvec = idx & (DVEC - 1);
    unsigned bt   = idx >> 8;  // log2(DVEC) = 8

    // DRAM-bound loads issue FIRST — nothing ahead of them.
    const float4* xr = x + (size_t)bt * (SDIM * DVEC) + dvec;
    float4 x0 = __ldcs(xr + 0 * DVEC);
    float4 x1 = __ldcs(xr + 1 * DVEC);
    float4 x2 = __ldcs(xr + 2 * DVEC);
    float4 x3 = __ldcs(xr + 3 * DVEC);
    float4 l  = __ldcs(lo + (size_t)bt * DVEC + dvec);

    // Warp-uniform broadcast loads (L1-resident): g and the 4 M columns.
    float4 gv = __ldg(&d_g4);

    const float4* bC = reinterpret_cast<const float4*>(d_biasC) + dvec;
    float4* outr = out + (size_t)bt * (SDIM * DVEC) + dvec;

#pragma unroll
    for (int s = 0; s < 4; s++) {
        float4 mc = __ldg(&d_Mt4[s]);      // {M[0][s],M[1][s],M[2][s],M[3][s]}
        float g = (s == 0) ? gv.x : (s == 1) ? gv.y : (s == 2) ? gv.z : gv.w;
        float4 b = __ldg(bC + s * DVEC);
        float4 o;
        o.x = fmaf(mc.x, x0.x, fmaf(mc.y, x1.x, fmaf(mc.z, x2.x, fmaf(mc.w, x3.x, fmaf(g, l.x, b.x)))));
        o.y = fmaf(mc.x, x0.y, fmaf(mc.y, x1.y, fmaf(mc.z, x2.y, fmaf(mc.w, x3.y, fmaf(g, l.y, b.y)))));
        o.z = fmaf(mc.x, x0.z, fmaf(mc.y, x1.z, fmaf(mc.z, x2.z, fmaf(mc.w, x3.z, fmaf(g, l.z, b.z)))));
        o.w = fmaf(mc.x, x0.w, fmaf(mc.y, x1.w, fmaf(mc.z, x2.w, fmaf(mc.w, x3.w, fmaf(g, l.w, b.w)))));
        __stcs(outr + s * DVEC, o);
    }
}

// ---------------------------------------------------------------------------
// Launch. Inputs per metadata order:
//   0: x (B,T,S,D) f32   1: layer_output (B,T,D) f32   2: H_res (S,S) f32
//   3: H_pos (S,1) f32   4: alpha_res f32 scalar        5: alpha_pos f32 scalar
//   6: bias_res (S,D)    7: bias_pos (S,D)
// ---------------------------------------------------------------------------
extern "C" void kernel_launch(void* const* d_in, const int* in_sizes, int n_in,
                              void* d_out, int out_size)
{
    const float* x         = (const float*)d_in[0];
    const float* lo        = (const float*)d_in[1];
    const float* H_res     = (const float*)d_in[2];
    const float* H_pos     = (const float*)d_in[3];
    const float* alpha_res = (const float*)d_in[4];
    const float* alpha_pos = (const float*)d_in[5];
    const float* bias_res  = (const float*)d_in[6];
    const float* bias_pos  = (const float*)d_in[7];
    float* out             = (float*)d_out;

    prep_kernel<<<1, 256>>>(H_res, H_pos, alpha_res, alpha_pos,
                            (const float4*)bias_res, (const float4*)bias_pos);

    const unsigned total = BT * DVEC;          // 2,097,152 threads
    mhc_residual_kernel<<<total / 64, 64>>>(
        (const float4*)x, (const float4*)lo, (float4*)out);
}

// round 16
// speedup vs baseline: 1.0347x; 1.0198x over previous
#include <cuda_runtime.h>
#include <cstdint>

// Problem constants (fixed by the reference: B=4, T=2048, S=4, D=1024)
#define BT      8192        // B*T
#define SDIM    4
#define DDIM    1024
#define DVEC    256         // D/4 float4 per row
#define SINKHORN_ITERS 20
#define EPS_SK  1e-8f

// Device-side scratch (allocation-free rule: use __device__ globals)
__device__ float4 d_Mt4[4];             // column s of M: {M[0][s],M[1][s],M[2][s],M[3][s]}
__device__ float4 d_g4;                 // {g0,g1,g2,g3} = alpha_pos * H_pos
__device__ float  d_biasC[SDIM * DDIM]; // bias_res + bias_pos, [s][d]

__device__ __forceinline__ float rcp_approx(float x) {
    float r;
    asm("rcp.approx.f32 %0, %1;" : "=f"(r) : "f"(x));
    return r;
}

// ---------------------------------------------------------------------------
// Prep (~1us): warp-parallel 4x4 Sinkhorn on lanes 0..15 (shfl reductions,
// rcp.approx) while the whole 256-thread block folds the 16KB bias via float4.
// Emits M TRANSPOSED as 4 float4 columns (single broadcast LDG.128 per
// output stream in the main kernel).
// ---------------------------------------------------------------------------
__global__ __launch_bounds__(256)
void prep_kernel(const float*  __restrict__ H_res,
                 const float*  __restrict__ H_pos,
                 const float*  __restrict__ alpha_res,
                 const float*  __restrict__ alpha_pos,
                 const float4* __restrict__ br,
                 const float4* __restrict__ bp)
{
    const unsigned tid = threadIdx.x;

    // Bias fold: 1024 float4, 4 per thread
    float4* biasC4 = reinterpret_cast<float4*>(d_biasC);
    #pragma unroll
    for (int i = 0; i < 4; i++) {
        unsigned j = tid + i * 256;
        float4 a = __ldg(br + j);
        float4 c = __ldg(bp + j);
        float4 b;
        b.x = a.x + c.x; b.y = a.y + c.y; b.z = a.z + c.z; b.w = a.w + c.w;
        biasC4[j] = b;
    }

    // Warp 0, lanes 0..15: Sinkhorn. lane = r*4 + c holds P[r][c].
    if (tid < 16) {
        const unsigned lane = tid;
        float h = __ldg(H_res + lane);
        float m = fmaxf(h, __shfl_xor_sync(0xffffu, h, 1));
        m = fmaxf(m, __shfl_xor_sync(0xffffu, m, 2));
        float v = __expf(h - m);
        #pragma unroll 1
        for (int it = 0; it < SINKHORN_ITERS; it++) {
            float s = v + __shfl_xor_sync(0xffffu, v, 1);   // row sum (over c)
            s += __shfl_xor_sync(0xffffu, s, 2);
            v *= rcp_approx(s + EPS_SK);
            float t = v + __shfl_xor_sync(0xffffu, v, 4);   // col sum (over r)
            t += __shfl_xor_sync(0xffffu, t, 8);
            v *= rcp_approx(t + EPS_SK);
        }
        float ar = __ldg(alpha_res);
        float diag = ((lane >> 2) == (lane & 3)) ? 1.0f : 0.0f;
        float mval = diag + ar * v;                 // M[r][c], lane = r*4 + c

        // Transpose via shfl: column s = {lanes s, 4+s, 8+s, 12+s}
        float c0 = __shfl_sync(0xffffu, mval, (lane & 3) + 0);
        float c1 = __shfl_sync(0xffffu, mval, (lane & 3) + 4);
        float c2 = __shfl_sync(0xffffu, mval, (lane & 3) + 8);
        float c3 = __shfl_sync(0xffffu, mval, (lane & 3) + 12);
        if (lane < 4) {
            d_Mt4[lane] = make_float4(c0, c1, c2, c3);
        }
        if (lane == 0) {
            float ap = __ldg(alpha_pos);
            d_g4 = make_float4(ap * __ldg(H_pos + 0), ap * __ldg(H_pos + 1),
                               ap * __ldg(H_pos + 2), ap * __ldg(H_pos + 3));
        }
    }
}

// ---------------------------------------------------------------------------
// Main kernel — the measured session optimum (R14 configuration):
//   * 128-thread CTAs, grid 16384, __launch_bounds__(128, 8):
//     8 CTAs/SM at 64 regs (RF exactly full, 32 warps/SM). The CTA-size
//     sweep is a measured parabola: 256thr 41.2us / 128thr 40.2us /
//     64thr 41.7us — 128 is the optimum.
//   * Barrier-free: no smem, no __syncthreads; the 5 streaming DRAM loads
//     are the block's first instructions.
//   * __ldcs on the zero-reuse x/lo streams, __stcs on the never-re-read
//     output stream, __ldg broadcast for M columns / g / bias (L1/L2-hot).
//   * Register sweep also a parabola: 48r 46.2 / 64r 41.0 / 66r 44.1 /
//     80r 45.0 -> 64 regs.
// Measured: 40.2us @ 78.1% DRAM (6.18 TB/s) — ~roofline for the mandatory
// 288 MB of HBM traffic.
//   out[bt,s,dv] = sum_sp M[sp][s]*x[bt,sp,dv] + g[s]*lo[bt,dv] + biasC[s,dv]
// ---------------------------------------------------------------------------
__global__ __launch_bounds__(128, 8)
void mhc_residual_kernel(const float4* __restrict__ x,
                         const float4* __restrict__ lo,
                         float4* __restrict__ out)
{
    unsigned idx = blockIdx.x * 128u + threadIdx.x;  // 0 .. BT*DVEC-1
    unsigned dvec = idx & (DVEC - 1);
    unsigned bt   = idx >> 8;  // log2(DVEC) = 8

    // DRAM-bound loads issue FIRST — nothing ahead of them.
    const float4* xr = x + (size_t)bt * (SDIM * DVEC) + dvec;
    float4 x0 = __ldcs(xr + 0 * DVEC);
    float4 x1 = __ldcs(xr + 1 * DVEC);
    float4 x2 = __ldcs(xr + 2 * DVEC);
    float4 x3 = __ldcs(xr + 3 * DVEC);
    float4 l  = __ldcs(lo + (size_t)bt * DVEC + dvec);

    // Warp-uniform broadcast loads (L1-resident): g and the 4 M columns.
    float4 gv = __ldg(&d_g4);

    const float4* bC = reinterpret_cast<const float4*>(d_biasC) + dvec;
    float4* outr = out + (size_t)bt * (SDIM * DVEC) + dvec;

#pragma unroll
    for (int s = 0; s < 4; s++) {
        float4 mc = __ldg(&d_Mt4[s]);      // {M[0][s],M[1][s],M[2][s],M[3][s]}
        float g = (s == 0) ? gv.x : (s == 1) ? gv.y : (s == 2) ? gv.z : gv.w;
        float4 b = __ldg(bC + s * DVEC);
        float4 o;
        o.x = fmaf(mc.x, x0.x, fmaf(mc.y, x1.x, fmaf(mc.z, x2.x, fmaf(mc.w, x3.x, fmaf(g, l.x, b.x)))));
        o.y = fmaf(mc.x, x0.y, fmaf(mc.y, x1.y, fmaf(mc.z, x2.y, fmaf(mc.w, x3.y, fmaf(g, l.y, b.y)))));
        o.z = fmaf(mc.x, x0.z, fmaf(mc.y, x1.z, fmaf(mc.z, x2.z, fmaf(mc.w, x3.z, fmaf(g, l.z, b.z)))));
        o.w = fmaf(mc.x, x0.w, fmaf(mc.y, x1.w, fmaf(mc.z, x2.w, fmaf(mc.w, x3.w, fmaf(g, l.w, b.w)))));
        __stcs(outr + s * DVEC, o);
    }
}

// ---------------------------------------------------------------------------
// Launch. Inputs per metadata order:
//   0: x (B,T,S,D) f32   1: layer_output (B,T,D) f32   2: H_res (S,S) f32
//   3: H_pos (S,1) f32   4: alpha_res f32 scalar        5: alpha_pos f32 scalar
//   6: bias_res (S,D)    7: bias_pos (S,D)
// ---------------------------------------------------------------------------
extern "C" void kernel_launch(void* const* d_in, const int* in_sizes, int n_in,
                              void* d_out, int out_size)
{
    const float* x         = (const float*)d_in[0];
    const float* lo        = (const float*)d_in[1];
    const float* H_res     = (const float*)d_in[2];
    const float* H_pos     = (const float*)d_in[3];
    const float* alpha_res = (const float*)d_in[4];
    const float* alpha_pos = (const float*)d_in[5];
    const float* bias_res  = (const float*)d_in[6];
    const float* bias_pos  = (const float*)d_in[7];
    float* out             = (float*)d_out;

    prep_kernel<<<1, 256>>>(H_res, H_pos, alpha_res, alpha_pos,
                            (const float4*)bias_res, (const float4*)bias_pos);

    const unsigned total = BT * DVEC;          // 2,097,152 threads
    mhc_residual_kernel<<<total / 128, 128>>>(
        (const float4*)x, (const float4*)lo, (float4*)out);
}